// round 5
// baseline (speedup 1.0000x reference)
#include <cuda_runtime.h>

// Problem shape (fixed by the dataset)
#define BB 16
#define TT 16384
#define CC 64

// Chunked IIR: W warmup steps from zero state (transient ~0.831^48 ~ 1.4e-4;
// measured rel_err 7e-5 at W=48/L=64; L=32 doubles seams -> ~1e-4), then L
// output steps. Chunk 0 starts at t=0 exactly (true zero state).
#define CHUNK_L 32
#define WARM    48
#define NCHUNK  (TT / CHUNK_L)   // 512

typedef unsigned long long u64;

// ---- packed f32x2 helpers (sm_103a FFMA2 path; PTX-only per ptxas) ----
__device__ __forceinline__ u64 bcast2(float v) {
    u64 r; asm("mov.b64 %0, {%1, %1};" : "=l"(r) : "f"(v)); return r;
}
__device__ __forceinline__ u64 fma2(u64 a, u64 b, u64 c) {
    u64 d; asm("fma.rn.f32x2 %0, %1, %2, %3;" : "=l"(d) : "l"(a), "l"(b), "l"(c)); return d;
}
__device__ __forceinline__ u64 mul2(u64 a, u64 b) {
    u64 d; asm("mul.rn.f32x2 %0, %1, %2;" : "=l"(d) : "l"(a), "l"(b)); return d;
}

struct CoeffsP {
    // bandpass sections (b1 == 0 by construction: proto zeros at z=+1,-1)
    u64 p0_b0, p0_b2, p0_na1, p0_na2;
    u64 p1_b0, p1_b2, p1_na1, p1_na2;
    // lowpass sections (generic)
    u64 q0_b0, q0_b1, q0_b2, q0_na1, q0_na2;
    u64 q1_b0, q1_b1, q1_b2, q1_na1, q1_na2;
};

// bp biquad, b1 = 0: 4 packed ops
__device__ __forceinline__ u64 biquad_bp(u64 x, u64 b0, u64 b2, u64 na1, u64 na2,
                                         u64& s1, u64& s2)
{
    u64 y = fma2(b0, x, s1);
    s1 = fma2(na1, y, s2);
    s2 = fma2(na2, y, mul2(b2, x));
    return y;
}

// generic biquad: 5 packed ops
__device__ __forceinline__ u64 biquad_g(u64 x, u64 b0, u64 b1, u64 b2, u64 na1, u64 na2,
                                        u64& s1, u64& s2)
{
    u64 y = fma2(b0, x, s1);
    u64 t = fma2(b1, x, s2);
    s1 = fma2(na1, y, t);
    s2 = fma2(na2, y, mul2(b2, x));
    return y;
}

__device__ __forceinline__ u64 pipeline_step(u64 v, const CoeffsP& k,
                                             u64& s1a, u64& s2a, u64& s1b, u64& s2b,
                                             u64& s1c, u64& s2c, u64& s1d, u64& s2d)
{
    u64 y = biquad_bp(v, k.p0_b0, k.p0_b2, k.p0_na1, k.p0_na2, s1a, s2a);
    y     = biquad_bp(y, k.p1_b0, k.p1_b2, k.p1_na1, k.p1_na2, s1b, s2b);
    y     = mul2(y, y);
    y     = biquad_g(y, k.q0_b0, k.q0_b1, k.q0_b2, k.q0_na1, k.q0_na2, s1c, s2c);
    y     = biquad_g(y, k.q1_b0, k.q1_b1, k.q1_b2, k.q1_na1, k.q1_na2, s1d, s2d);
    return y;
}

__device__ __forceinline__ u64 ldg64(const float* p) {
    u64 v; asm("ld.global.nc.b64 %0, [%1];" : "=l"(v) : "l"(p)); return v;
}
__device__ __forceinline__ void stcs64(float* p, u64 v) {
    asm volatile("st.global.cs.b64 [%0], %1;" :: "l"(p), "l"(v) : "memory");
}

__global__ void __launch_bounds__(256)
iir_chunked_kernel(const float* __restrict__ x,
                   const float* __restrict__ bp_sos,
                   const float* __restrict__ lp_sos,
                   float* __restrict__ out)
{
    const int c2    = threadIdx.x;                              // 0..31 (channel pair)
    const int b     = blockIdx.x;                               // 0..15 (batch)
    const int chunk = blockIdx.y * blockDim.y + threadIdx.y;    // 0..NCHUNK-1

    // ---- Load & normalize the 4 biquad sections (2 bp, 2 lp) ----
    // sos row layout: [b0, b1, b2, a0, a1, a2]
    CoeffsP k;
    {
        const float* r0 = bp_sos;
        const float* r1 = bp_sos + 6;
        const float* r2 = lp_sos;
        const float* r3 = lp_sos + 6;
        float i0 = 1.0f / r0[3], i1 = 1.0f / r1[3], i2 = 1.0f / r2[3], i3 = 1.0f / r3[3];
        k.p0_b0 = bcast2(r0[0] * i0); k.p0_b2 = bcast2(r0[2] * i0);
        k.p0_na1 = bcast2(-r0[4] * i0); k.p0_na2 = bcast2(-r0[5] * i0);
        k.p1_b0 = bcast2(r1[0] * i1); k.p1_b2 = bcast2(r1[2] * i1);
        k.p1_na1 = bcast2(-r1[4] * i1); k.p1_na2 = bcast2(-r1[5] * i1);
        k.q0_b0 = bcast2(r2[0] * i2); k.q0_b1 = bcast2(r2[1] * i2); k.q0_b2 = bcast2(r2[2] * i2);
        k.q0_na1 = bcast2(-r2[4] * i2); k.q0_na2 = bcast2(-r2[5] * i2);
        k.q1_b0 = bcast2(r3[0] * i3); k.q1_b1 = bcast2(r3[1] * i3); k.q1_b2 = bcast2(r3[2] * i3);
        k.q1_na1 = bcast2(-r3[4] * i3); k.q1_na2 = bcast2(-r3[5] * i3);
    }

    // ---- Filter states (zero-initialized, packed 2 channels) ----
    u64 s1a = 0, s2a = 0, s1b = 0, s2b = 0;
    u64 s1c = 0, s2c = 0, s1d = 0, s2d = 0;

    const int t_out0 = chunk * CHUNK_L;
    const int warm   = (chunk == 0) ? 0 : WARM;        // warp-uniform (y fixed per warp)
    const int steps  = warm + CHUNK_L;                 // multiple of 4

    const float* xp = x + ((size_t)b * TT + (size_t)(t_out0 - warm)) * CC + 2 * c2;
    float*       op = out + ((size_t)b * TT + (size_t)t_out0) * CC + 2 * c2;

    // ---- Software-pipelined fused loop: prefetch next 4-step batch while
    //      computing the current one. Stores only once past warmup. ----
    u64 v0 = ldg64(xp + 0 * CC);
    u64 v1 = ldg64(xp + 1 * CC);
    u64 v2 = ldg64(xp + 2 * CC);
    u64 v3 = ldg64(xp + 3 * CC);
    xp += 4 * CC;

    for (int g = 0; g < steps; g += 4) {
        // prefetch next batch (clamped on the last group: re-read, in bounds)
        const float* pf = (g + 4 < steps) ? xp : (xp - 4 * CC);
        u64 n0 = ldg64(pf + 0 * CC);
        u64 n1 = ldg64(pf + 1 * CC);
        u64 n2 = ldg64(pf + 2 * CC);
        u64 n3 = ldg64(pf + 3 * CC);

        u64 y0 = pipeline_step(v0, k, s1a, s2a, s1b, s2b, s1c, s2c, s1d, s2d);
        u64 y1 = pipeline_step(v1, k, s1a, s2a, s1b, s2b, s1c, s2c, s1d, s2d);
        u64 y2 = pipeline_step(v2, k, s1a, s2a, s1b, s2b, s1c, s2c, s1d, s2d);
        u64 y3 = pipeline_step(v3, k, s1a, s2a, s1b, s2b, s1c, s2c, s1d, s2d);

        if (g >= warm) {   // warp-uniform branch; warm and CHUNK_L are multiples of 4
            stcs64(op + 0 * CC, y0);
            stcs64(op + 1 * CC, y1);
            stcs64(op + 2 * CC, y2);
            stcs64(op + 3 * CC, y3);
            op += 4 * CC;
        }

        v0 = n0; v1 = n1; v2 = n2; v3 = n3;
        xp += 4 * CC;
    }
}

extern "C" void kernel_launch(void* const* d_in, const int* in_sizes, int n_in,
                              void* d_out, int out_size)
{
    const float* x      = (const float*)d_in[0];
    const float* bp_sos = (const float*)d_in[1];
    const float* lp_sos = (const float*)d_in[2];
    float* out          = (float*)d_out;

    dim3 blk(32, 8);                 // 256 threads: 32 channel-pairs x 8 chunks
    dim3 grd(BB, NCHUNK / 8);        // 16 x 64 = 1024 blocks
    iir_chunked_kernel<<<grd, blk>>>(x, bp_sos, lp_sos, out);
}

// round 6
// speedup vs baseline: 1.5112x; 1.5112x over previous
#include <cuda_runtime.h>

// Problem shape (fixed by the dataset)
#define BB 16
#define TT 16384
#define CC 64

// Chunked IIR: W warmup steps from zero state, then L output steps.
// Transient ~0.831^40 ~ 6e-4 of state; measured rel_err 7e-5 at W=48 scales
// by 0.831^-8 ~ 4.4 -> ~3e-4, under the 1e-3 gate.
// Chunk 0 starts at t=0 exactly (true zero state).
#define CHUNK_L 64
#define WARM    40            // WARM + CHUNK_L = 104 = 13 * 8
#define NCHUNK  (TT / CHUNK_L)   // 256
#define GRP     8

typedef unsigned long long u64;

// ---- packed f32x2 helpers (sm_103a FFMA2 path; PTX-only per ptxas) ----
__device__ __forceinline__ u64 bcast2(float v) {
    u64 r; asm("mov.b64 %0, {%1, %1};" : "=l"(r) : "f"(v)); return r;
}
__device__ __forceinline__ u64 fma2(u64 a, u64 b, u64 c) {
    u64 d; asm("fma.rn.f32x2 %0, %1, %2, %3;" : "=l"(d) : "l"(a), "l"(b), "l"(c)); return d;
}
__device__ __forceinline__ u64 mul2(u64 a, u64 b) {
    u64 d; asm("mul.rn.f32x2 %0, %1, %2;" : "=l"(d) : "l"(a), "l"(b)); return d;
}

struct CoeffsP {
    // bandpass sections (b1 == 0 by construction: proto zeros at z=+1,-1)
    u64 p0_b0, p0_b2, p0_na1, p0_na2;
    u64 p1_b0, p1_b2, p1_na1, p1_na2;
    // lowpass sections (generic)
    u64 q0_b0, q0_b1, q0_b2, q0_na1, q0_na2;
    u64 q1_b0, q1_b1, q1_b2, q1_na1, q1_na2;
};

// bp biquad, b1 = 0: 4 packed ops
__device__ __forceinline__ u64 biquad_bp(u64 x, u64 b0, u64 b2, u64 na1, u64 na2,
                                         u64& s1, u64& s2)
{
    u64 y = fma2(b0, x, s1);
    s1 = fma2(na1, y, s2);
    s2 = fma2(na2, y, mul2(b2, x));
    return y;
}

// generic biquad: 5 packed ops
__device__ __forceinline__ u64 biquad_g(u64 x, u64 b0, u64 b1, u64 b2, u64 na1, u64 na2,
                                        u64& s1, u64& s2)
{
    u64 y = fma2(b0, x, s1);
    u64 t = fma2(b1, x, s2);
    s1 = fma2(na1, y, t);
    s2 = fma2(na2, y, mul2(b2, x));
    return y;
}

__device__ __forceinline__ u64 pipeline_step(u64 v, const CoeffsP& k,
                                             u64& s1a, u64& s2a, u64& s1b, u64& s2b,
                                             u64& s1c, u64& s2c, u64& s1d, u64& s2d)
{
    u64 y = biquad_bp(v, k.p0_b0, k.p0_b2, k.p0_na1, k.p0_na2, s1a, s2a);
    y     = biquad_bp(y, k.p1_b0, k.p1_b2, k.p1_na1, k.p1_na2, s1b, s2b);
    y     = mul2(y, y);
    y     = biquad_g(y, k.q0_b0, k.q0_b1, k.q0_b2, k.q0_na1, k.q0_na2, s1c, s2c);
    y     = biquad_g(y, k.q1_b0, k.q1_b1, k.q1_b2, k.q1_na1, k.q1_na2, s1d, s2d);
    return y;
}

__device__ __forceinline__ u64 ldg64(const float* p) {
    u64 v; asm("ld.global.nc.b64 %0, [%1];" : "=l"(v) : "l"(p)); return v;
}
__device__ __forceinline__ void stcs64(float* p, u64 v) {
    asm volatile("st.global.cs.b64 [%0], %1;" :: "l"(p), "l"(v) : "memory");
}

__global__ void __launch_bounds__(256)
iir_chunked_kernel(const float* __restrict__ x,
                   const float* __restrict__ bp_sos,
                   const float* __restrict__ lp_sos,
                   float* __restrict__ out)
{
    const int c2    = threadIdx.x;                              // 0..31 (channel pair)
    const int b     = blockIdx.x;                               // 0..15 (batch)
    const int chunk = blockIdx.y * blockDim.y + threadIdx.y;    // 0..NCHUNK-1

    // ---- Load & normalize the 4 biquad sections (2 bp, 2 lp) ----
    // sos row layout: [b0, b1, b2, a0, a1, a2]
    CoeffsP k;
    {
        const float* r0 = bp_sos;
        const float* r1 = bp_sos + 6;
        const float* r2 = lp_sos;
        const float* r3 = lp_sos + 6;
        float i0 = 1.0f / r0[3], i1 = 1.0f / r1[3], i2 = 1.0f / r2[3], i3 = 1.0f / r3[3];
        k.p0_b0 = bcast2(r0[0] * i0); k.p0_b2 = bcast2(r0[2] * i0);
        k.p0_na1 = bcast2(-r0[4] * i0); k.p0_na2 = bcast2(-r0[5] * i0);
        k.p1_b0 = bcast2(r1[0] * i1); k.p1_b2 = bcast2(r1[2] * i1);
        k.p1_na1 = bcast2(-r1[4] * i1); k.p1_na2 = bcast2(-r1[5] * i1);
        k.q0_b0 = bcast2(r2[0] * i2); k.q0_b1 = bcast2(r2[1] * i2); k.q0_b2 = bcast2(r2[2] * i2);
        k.q0_na1 = bcast2(-r2[4] * i2); k.q0_na2 = bcast2(-r2[5] * i2);
        k.q1_b0 = bcast2(r3[0] * i3); k.q1_b1 = bcast2(r3[1] * i3); k.q1_b2 = bcast2(r3[2] * i3);
        k.q1_na1 = bcast2(-r3[4] * i3); k.q1_na2 = bcast2(-r3[5] * i3);
    }

    // ---- Filter states (zero-initialized, packed 2 channels) ----
    u64 s1a = 0, s2a = 0, s1b = 0, s2b = 0;
    u64 s1c = 0, s2c = 0, s1d = 0, s2d = 0;

    const int t_out0 = chunk * CHUNK_L;
    const int warm   = (chunk == 0) ? 0 : WARM;        // warp-uniform
    const int steps  = warm + CHUNK_L;                 // multiple of GRP (104 or 64)

    const float* xp = x + ((size_t)b * TT + (size_t)(t_out0 - warm)) * CC + 2 * c2;
    float*       op = out + ((size_t)b * TT + (size_t)t_out0) * CC + 2 * c2;

    // ---- Software-pipelined loop, 8 steps/group: prefetch next group's
    //      loads before computing the current group's recurrence. ----
    u64 v[GRP], n[GRP];
#pragma unroll
    for (int j = 0; j < GRP; ++j) v[j] = ldg64(xp + j * CC);
    xp += GRP * CC;

    for (int g = 0; g < steps; g += GRP) {
        // prefetch next batch (clamped on the last group: re-read, in bounds)
        const float* pf = (g + GRP < steps) ? xp : (xp - GRP * CC);
#pragma unroll
        for (int j = 0; j < GRP; ++j) n[j] = ldg64(pf + j * CC);

        u64 y[GRP];
#pragma unroll
        for (int j = 0; j < GRP; ++j)
            y[j] = pipeline_step(v[j], k, s1a, s2a, s1b, s2b, s1c, s2c, s1d, s2d);

        if (g >= warm) {   // warp-uniform; warm and CHUNK_L are multiples of 8
#pragma unroll
            for (int j = 0; j < GRP; ++j) stcs64(op + j * CC, y[j]);
            op += GRP * CC;
        }

#pragma unroll
        for (int j = 0; j < GRP; ++j) v[j] = n[j];
        xp += GRP * CC;
    }
}

extern "C" void kernel_launch(void* const* d_in, const int* in_sizes, int n_in,
                              void* d_out, int out_size)
{
    const float* x      = (const float*)d_in[0];
    const float* bp_sos = (const float*)d_in[1];
    const float* lp_sos = (const float*)d_in[2];
    float* out          = (float*)d_out;

    dim3 blk(32, 8);                 // 256 threads: 32 channel-pairs x 8 chunks
    dim3 grd(BB, NCHUNK / 8);        // 16 x 32 = 512 blocks
    iir_chunked_kernel<<<grd, blk>>>(x, bp_sos, lp_sos, out);
}

// round 7
// speedup vs baseline: 1.5166x; 1.0036x over previous
#include <cuda_runtime.h>

// Problem shape (fixed by the dataset)
#define BB 16
#define TT 16384
#define CC 64

// Chunked IIR: W warmup steps from zero state, then L output steps.
// Transient ~0.831^40 ~ 6e-4 of state; measured rel_err 3.1e-4 at this config.
// Chunk 0 starts at t=0 exactly (true zero state).
#define CHUNK_L 64
#define WARM    40
#define NCHUNK  (TT / CHUNK_L)   // 256
#define GRP     8
#define NW_GRP  (WARM / GRP)     // 5
#define NM_GRP  (CHUNK_L / GRP)  // 8

typedef unsigned long long u64;

// ---- packed f32x2 helpers (sm_103a FFMA2 path; PTX-only per ptxas) ----
__device__ __forceinline__ u64 bcast2(float v) {
    u64 r; asm("mov.b64 %0, {%1, %1};" : "=l"(r) : "f"(v)); return r;
}
__device__ __forceinline__ u64 fma2(u64 a, u64 b, u64 c) {
    u64 d; asm("fma.rn.f32x2 %0, %1, %2, %3;" : "=l"(d) : "l"(a), "l"(b), "l"(c)); return d;
}
__device__ __forceinline__ u64 mul2(u64 a, u64 b) {
    u64 d; asm("mul.rn.f32x2 %0, %1, %2;" : "=l"(d) : "l"(a), "l"(b)); return d;
}

struct CoeffsP {
    // bandpass sections (b1 == 0 by construction: proto zeros at z=+1,-1)
    u64 p0_b0, p0_b2, p0_na1, p0_na2;
    u64 p1_b0, p1_b2, p1_na1, p1_na2;
    // lowpass sections (generic)
    u64 q0_b0, q0_b1, q0_b2, q0_na1, q0_na2;
    u64 q1_b0, q1_b1, q1_b2, q1_na1, q1_na2;
};

// bp biquad, b1 = 0: 4 packed ops
__device__ __forceinline__ u64 biquad_bp(u64 x, u64 b0, u64 b2, u64 na1, u64 na2,
                                         u64& s1, u64& s2)
{
    u64 y = fma2(b0, x, s1);
    s1 = fma2(na1, y, s2);
    s2 = fma2(na2, y, mul2(b2, x));
    return y;
}

// generic biquad: 5 packed ops
__device__ __forceinline__ u64 biquad_g(u64 x, u64 b0, u64 b1, u64 b2, u64 na1, u64 na2,
                                        u64& s1, u64& s2)
{
    u64 y = fma2(b0, x, s1);
    u64 t = fma2(b1, x, s2);
    s1 = fma2(na1, y, t);
    s2 = fma2(na2, y, mul2(b2, x));
    return y;
}

__device__ __forceinline__ u64 pipeline_step(u64 v, const CoeffsP& k,
                                             u64& s1a, u64& s2a, u64& s1b, u64& s2b,
                                             u64& s1c, u64& s2c, u64& s1d, u64& s2d)
{
    u64 y = biquad_bp(v, k.p0_b0, k.p0_b2, k.p0_na1, k.p0_na2, s1a, s2a);
    y     = biquad_bp(y, k.p1_b0, k.p1_b2, k.p1_na1, k.p1_na2, s1b, s2b);
    y     = mul2(y, y);
    y     = biquad_g(y, k.q0_b0, k.q0_b1, k.q0_b2, k.q0_na1, k.q0_na2, s1c, s2c);
    y     = biquad_g(y, k.q1_b0, k.q1_b1, k.q1_b2, k.q1_na1, k.q1_na2, s1d, s2d);
    return y;
}

__device__ __forceinline__ u64 ldg64(const float* p) {
    u64 v; asm("ld.global.nc.b64 %0, [%1];" : "=l"(v) : "l"(p)); return v;
}
__device__ __forceinline__ void stcs64(float* p, u64 v) {
    asm volatile("st.global.cs.b64 [%0], %1;" :: "l"(p), "l"(v) : "memory");
}

__global__ void __launch_bounds__(128)
iir_chunked_kernel(const float* __restrict__ x,
                   const float* __restrict__ bp_sos,
                   const float* __restrict__ lp_sos,
                   float* __restrict__ out)
{
    const int c2    = threadIdx.x;                              // 0..31 (channel pair)
    const int b     = blockIdx.x;                               // 0..15 (batch)
    const int chunk = blockIdx.y * blockDim.y + threadIdx.y;    // 0..NCHUNK-1

    // ---- Load & normalize the 4 biquad sections (2 bp, 2 lp) ----
    // sos row layout: [b0, b1, b2, a0, a1, a2]
    CoeffsP k;
    {
        const float* r0 = bp_sos;
        const float* r1 = bp_sos + 6;
        const float* r2 = lp_sos;
        const float* r3 = lp_sos + 6;
        float i0 = 1.0f / r0[3], i1 = 1.0f / r1[3], i2 = 1.0f / r2[3], i3 = 1.0f / r3[3];
        k.p0_b0 = bcast2(r0[0] * i0); k.p0_b2 = bcast2(r0[2] * i0);
        k.p0_na1 = bcast2(-r0[4] * i0); k.p0_na2 = bcast2(-r0[5] * i0);
        k.p1_b0 = bcast2(r1[0] * i1); k.p1_b2 = bcast2(r1[2] * i1);
        k.p1_na1 = bcast2(-r1[4] * i1); k.p1_na2 = bcast2(-r1[5] * i1);
        k.q0_b0 = bcast2(r2[0] * i2); k.q0_b1 = bcast2(r2[1] * i2); k.q0_b2 = bcast2(r2[2] * i2);
        k.q0_na1 = bcast2(-r2[4] * i2); k.q0_na2 = bcast2(-r2[5] * i2);
        k.q1_b0 = bcast2(r3[0] * i3); k.q1_b1 = bcast2(r3[1] * i3); k.q1_b2 = bcast2(r3[2] * i3);
        k.q1_na1 = bcast2(-r3[4] * i3); k.q1_na2 = bcast2(-r3[5] * i3);
    }

    // ---- Filter states (zero-initialized, packed 2 channels) ----
    u64 s1a = 0, s2a = 0, s1b = 0, s2b = 0;
    u64 s1c = 0, s2c = 0, s1d = 0, s2d = 0;

    const int t_out0 = chunk * CHUNK_L;
    const float* xm = x + ((size_t)b * TT + (size_t)t_out0) * CC + 2 * c2;   // main base
    float*       op = out + ((size_t)b * TT + (size_t)t_out0) * CC + 2 * c2;

    u64 v[GRP];

    if (chunk != 0) {   // warp-uniform (chunk is fixed per warp)
        // ---- Warmup: 5 fully-unrolled groups, immediate offsets from xw.
        //      Group g prefetches group g+1; last group prefetches main grp 0.
        const float* xw = xm - (size_t)WARM * CC;
#pragma unroll
        for (int j = 0; j < GRP; ++j) v[j] = ldg64(xw + j * CC);
#pragma unroll
        for (int g = 0; g < NW_GRP; ++g) {
            u64 n[GRP];
#pragma unroll
            for (int j = 0; j < GRP; ++j) {
                n[j] = (g + 1 < NW_GRP) ? ldg64(xw + ((g + 1) * GRP + j) * CC)
                                        : ldg64(xm + j * CC);
            }
#pragma unroll
            for (int j = 0; j < GRP; ++j)
                (void)pipeline_step(v[j], k, s1a, s2a, s1b, s2b, s1c, s2c, s1d, s2d);
#pragma unroll
            for (int j = 0; j < GRP; ++j) v[j] = n[j];
        }
    } else {
#pragma unroll
        for (int j = 0; j < GRP; ++j) v[j] = ldg64(xm + j * CC);
    }

    // ---- Main: 8 fully-unrolled groups, immediate offsets, streaming stores ----
#pragma unroll
    for (int g = 0; g < NM_GRP; ++g) {
        u64 n[GRP];
        if (g + 1 < NM_GRP) {
#pragma unroll
            for (int j = 0; j < GRP; ++j)
                n[j] = ldg64(xm + ((g + 1) * GRP + j) * CC);
        }
        u64 y[GRP];
#pragma unroll
        for (int j = 0; j < GRP; ++j)
            y[j] = pipeline_step(v[j], k, s1a, s2a, s1b, s2b, s1c, s2c, s1d, s2d);
#pragma unroll
        for (int j = 0; j < GRP; ++j)
            stcs64(op + (g * GRP + j) * CC, y[j]);
        if (g + 1 < NM_GRP) {
#pragma unroll
            for (int j = 0; j < GRP; ++j) v[j] = n[j];
        }
    }
}

extern "C" void kernel_launch(void* const* d_in, const int* in_sizes, int n_in,
                              void* d_out, int out_size)
{
    const float* x      = (const float*)d_in[0];
    const float* bp_sos = (const float*)d_in[1];
    const float* lp_sos = (const float*)d_in[2];
    float* out          = (float*)d_out;

    dim3 blk(32, 4);                 // 128 threads: 32 channel-pairs x 4 chunks
    dim3 grd(BB, NCHUNK / 4);        // 16 x 64 = 1024 blocks
    iir_chunked_kernel<<<grd, blk>>>(x, bp_sos, lp_sos, out);
}

// round 8
// speedup vs baseline: 1.5366x; 1.0132x over previous
#include <cuda_runtime.h>

// Problem shape (fixed by the dataset)
#define BB 16
#define TT 16384
#define CC 64

// Chunked IIR: W warmup steps from zero state, then L output steps.
// Transient ~0.831^40 ~ 6e-4 of state; measured rel_err 3.06e-4 at this config.
// Chunk 0 starts at t=0 exactly (true zero state).
#define CHUNK_L 64
#define WARM    40
#define NCHUNK  (TT / CHUNK_L)   // 256
#define GRP     4
#define NWPAIR  (WARM / (2 * GRP))     // 5  warmup ping-pong iterations
#define NMPAIR  (CHUNK_L / (2 * GRP))  // 8  main ping-pong iterations

typedef unsigned long long u64;

// ---- packed f32x2 helpers (sm_103a FFMA2 path; PTX-only per ptxas) ----
__device__ __forceinline__ u64 bcast2(float v) {
    u64 r; asm("mov.b64 %0, {%1, %1};" : "=l"(r) : "f"(v)); return r;
}
__device__ __forceinline__ u64 fma2(u64 a, u64 b, u64 c) {
    u64 d; asm("fma.rn.f32x2 %0, %1, %2, %3;" : "=l"(d) : "l"(a), "l"(b), "l"(c)); return d;
}
__device__ __forceinline__ u64 mul2(u64 a, u64 b) {
    u64 d; asm("mul.rn.f32x2 %0, %1, %2;" : "=l"(d) : "l"(a), "l"(b)); return d;
}

struct CoeffsP {
    // bandpass sections (b1 == 0 by construction: proto zeros at z=+1,-1)
    u64 p0_b0, p0_b2, p0_na1, p0_na2;
    u64 p1_b0, p1_b2, p1_na1, p1_na2;
    // lowpass sections (generic)
    u64 q0_b0, q0_b1, q0_b2, q0_na1, q0_na2;
    u64 q1_b0, q1_b1, q1_b2, q1_na1, q1_na2;
};

// bp biquad, b1 = 0: 4 packed ops
__device__ __forceinline__ u64 biquad_bp(u64 x, u64 b0, u64 b2, u64 na1, u64 na2,
                                         u64& s1, u64& s2)
{
    u64 y = fma2(b0, x, s1);
    s1 = fma2(na1, y, s2);
    s2 = fma2(na2, y, mul2(b2, x));
    return y;
}

// generic biquad: 5 packed ops
__device__ __forceinline__ u64 biquad_g(u64 x, u64 b0, u64 b1, u64 b2, u64 na1, u64 na2,
                                        u64& s1, u64& s2)
{
    u64 y = fma2(b0, x, s1);
    u64 t = fma2(b1, x, s2);
    s1 = fma2(na1, y, t);
    s2 = fma2(na2, y, mul2(b2, x));
    return y;
}

__device__ __forceinline__ u64 ldg64(const float* p) {
    u64 v; asm("ld.global.nc.b64 %0, [%1];" : "=l"(v) : "l"(p)); return v;
}
__device__ __forceinline__ void stcs64(float* p, u64 v) {
    asm volatile("st.global.cs.b64 [%0], %1;" :: "l"(p), "l"(v) : "memory");
}

struct State {
    u64 s1a, s2a, s1b, s2b, s1c, s2c, s1d, s2d;
};

__device__ __forceinline__ u64 pipeline_step(u64 v, const CoeffsP& k, State& s)
{
    u64 y = biquad_bp(v, k.p0_b0, k.p0_b2, k.p0_na1, k.p0_na2, s.s1a, s.s2a);
    y     = biquad_bp(y, k.p1_b0, k.p1_b2, k.p1_na1, k.p1_na2, s.s1b, s.s2b);
    y     = mul2(y, y);
    y     = biquad_g(y, k.q0_b0, k.q0_b1, k.q0_b2, k.q0_na1, k.q0_na2, s.s1c, s.s2c);
    y     = biquad_g(y, k.q1_b0, k.q1_b1, k.q1_b2, k.q1_na1, k.q1_na2, s.s1d, s.s2d);
    return y;
}

__global__ void __launch_bounds__(128)
iir_chunked_kernel(const float* __restrict__ x,
                   const float* __restrict__ bp_sos,
                   const float* __restrict__ lp_sos,
                   float* __restrict__ out)
{
    const int c2    = threadIdx.x;                              // 0..31 (channel pair)
    const int b     = blockIdx.x;                               // 0..15 (batch)
    const int chunk = blockIdx.y * blockDim.y + threadIdx.y;    // 0..NCHUNK-1

    // ---- Load & normalize the 4 biquad sections (2 bp, 2 lp) ----
    // sos row layout: [b0, b1, b2, a0, a1, a2]
    CoeffsP k;
    {
        const float* r0 = bp_sos;
        const float* r1 = bp_sos + 6;
        const float* r2 = lp_sos;
        const float* r3 = lp_sos + 6;
        float i0 = 1.0f / r0[3], i1 = 1.0f / r1[3], i2 = 1.0f / r2[3], i3 = 1.0f / r3[3];
        k.p0_b0 = bcast2(r0[0] * i0); k.p0_b2 = bcast2(r0[2] * i0);
        k.p0_na1 = bcast2(-r0[4] * i0); k.p0_na2 = bcast2(-r0[5] * i0);
        k.p1_b0 = bcast2(r1[0] * i1); k.p1_b2 = bcast2(r1[2] * i1);
        k.p1_na1 = bcast2(-r1[4] * i1); k.p1_na2 = bcast2(-r1[5] * i1);
        k.q0_b0 = bcast2(r2[0] * i2); k.q0_b1 = bcast2(r2[1] * i2); k.q0_b2 = bcast2(r2[2] * i2);
        k.q0_na1 = bcast2(-r2[4] * i2); k.q0_na2 = bcast2(-r2[5] * i2);
        k.q1_b0 = bcast2(r3[0] * i3); k.q1_b1 = bcast2(r3[1] * i3); k.q1_b2 = bcast2(r3[2] * i3);
        k.q1_na1 = bcast2(-r3[4] * i3); k.q1_na2 = bcast2(-r3[5] * i3);
    }

    State st = {0, 0, 0, 0, 0, 0, 0, 0};

    const int t_out0 = chunk * CHUNK_L;
    const float* xm = x + ((size_t)b * TT + (size_t)t_out0) * CC + 2 * c2;   // main base
    float*       op = out + ((size_t)b * TT + (size_t)t_out0) * CC + 2 * c2;

    // Ping-pong buffers: A and B each hold one GRP=4 group. No rotate copies —
    // roles alternate structurally; prefetch distance ~1.5 groups.
    u64 vA[GRP], vB[GRP];
    const float* xg;   // next load position

    if (chunk != 0) {   // warp-uniform branch (chunk fixed per warp)
        const float* xw = xm - (size_t)WARM * CC;
#pragma unroll
        for (int j = 0; j < GRP; ++j) vA[j] = ldg64(xw + j * CC);
#pragma unroll
        for (int j = 0; j < GRP; ++j) vB[j] = ldg64(xw + (GRP + j) * CC);
        xg = xw + 2 * GRP * CC;

        // ---- Warmup: 5 ping-pong iterations = 10 groups = 40 steps ----
        for (int it = 0; it < NWPAIR; ++it) {
#pragma unroll
            for (int j = 0; j < GRP; ++j) (void)pipeline_step(vA[j], k, st);
#pragma unroll
            for (int j = 0; j < GRP; ++j) vA[j] = ldg64(xg + j * CC);
            xg += GRP * CC;
#pragma unroll
            for (int j = 0; j < GRP; ++j) (void)pipeline_step(vB[j], k, st);
#pragma unroll
            for (int j = 0; j < GRP; ++j) vB[j] = ldg64(xg + j * CC);
            xg += GRP * CC;
        }
        // Now vA = main group 0, vB = main group 1, xg -> main group 2.
    } else {
#pragma unroll
        for (int j = 0; j < GRP; ++j) vA[j] = ldg64(xm + j * CC);
#pragma unroll
        for (int j = 0; j < GRP; ++j) vB[j] = ldg64(xm + (GRP + j) * CC);
        xg = xm + 2 * GRP * CC;
    }

    // ---- Main: 8 ping-pong iterations = 16 groups = 64 outputs.
    //      Last iteration is an epilogue without loads (no OOB reads). ----
    for (int it = 0; it < NMPAIR - 1; ++it) {
#pragma unroll
        for (int j = 0; j < GRP; ++j) stcs64(op + j * CC, pipeline_step(vA[j], k, st));
#pragma unroll
        for (int j = 0; j < GRP; ++j) vA[j] = ldg64(xg + j * CC);
        xg += GRP * CC;
        op += GRP * CC;
#pragma unroll
        for (int j = 0; j < GRP; ++j) stcs64(op + j * CC, pipeline_step(vB[j], k, st));
#pragma unroll
        for (int j = 0; j < GRP; ++j) vB[j] = ldg64(xg + j * CC);
        xg += GRP * CC;
        op += GRP * CC;
    }
    // Epilogue: last two groups, no prefetch.
#pragma unroll
    for (int j = 0; j < GRP; ++j) stcs64(op + j * CC, pipeline_step(vA[j], k, st));
    op += GRP * CC;
#pragma unroll
    for (int j = 0; j < GRP; ++j) stcs64(op + j * CC, pipeline_step(vB[j], k, st));
}

extern "C" void kernel_launch(void* const* d_in, const int* in_sizes, int n_in,
                              void* d_out, int out_size)
{
    const float* x      = (const float*)d_in[0];
    const float* bp_sos = (const float*)d_in[1];
    const float* lp_sos = (const float*)d_in[2];
    float* out          = (float*)d_out;

    dim3 blk(32, 4);                 // 128 threads: 32 channel-pairs x 4 chunks
    dim3 grd(BB, NCHUNK / 4);        // 16 x 64 = 1024 blocks
    iir_chunked_kernel<<<grd, blk>>>(x, bp_sos, lp_sos, out);
}

// round 9
// speedup vs baseline: 1.6347x; 1.0639x over previous
#include <cuda_runtime.h>

// Problem shape (fixed by the dataset)
#define BB 16
#define TT 16384
#define CC 64

// Chunked IIR: W warmup steps from zero state, then L output steps.
// Transient ~0.831^40 ~ 6e-4 of state; measured rel_err 3.06e-4 at this config.
// Chunk 0 starts at t=0 exactly (true zero state).
#define CHUNK_L 64
#define WARM    40
#define NCHUNK  (TT / CHUNK_L)   // 256
#define GRP     8
#define WGRPS   (WARM / GRP)     // 5 warmup groups

typedef unsigned long long u64;

// ---- packed f32x2 helpers (sm_103a FFMA2 path; PTX-only per ptxas) ----
__device__ __forceinline__ u64 bcast2(float v) {
    u64 r; asm("mov.b64 %0, {%1, %1};" : "=l"(r) : "f"(v)); return r;
}
__device__ __forceinline__ u64 fma2(u64 a, u64 b, u64 c) {
    u64 d; asm("fma.rn.f32x2 %0, %1, %2, %3;" : "=l"(d) : "l"(a), "l"(b), "l"(c)); return d;
}
__device__ __forceinline__ u64 mul2(u64 a, u64 b) {
    u64 d; asm("mul.rn.f32x2 %0, %1, %2;" : "=l"(d) : "l"(a), "l"(b)); return d;
}

struct CoeffsP {
    // bandpass sections (b1 == 0 by construction: proto zeros at z=+1,-1)
    u64 p0_b0, p0_b2, p0_na1, p0_na2;
    u64 p1_b0, p1_b2, p1_na1, p1_na2;
    // lowpass sections (generic)
    u64 q0_b0, q0_b1, q0_b2, q0_na1, q0_na2;
    u64 q1_b0, q1_b1, q1_b2, q1_na1, q1_na2;
};

// bp biquad, b1 = 0: 4 packed ops
__device__ __forceinline__ u64 biquad_bp(u64 x, u64 b0, u64 b2, u64 na1, u64 na2,
                                         u64& s1, u64& s2)
{
    u64 y = fma2(b0, x, s1);
    s1 = fma2(na1, y, s2);
    s2 = fma2(na2, y, mul2(b2, x));
    return y;
}

// generic biquad: 5 packed ops
__device__ __forceinline__ u64 biquad_g(u64 x, u64 b0, u64 b1, u64 b2, u64 na1, u64 na2,
                                        u64& s1, u64& s2)
{
    u64 y = fma2(b0, x, s1);
    u64 t = fma2(b1, x, s2);
    s1 = fma2(na1, y, t);
    s2 = fma2(na2, y, mul2(b2, x));
    return y;
}

__device__ __forceinline__ u64 ldg64(const float* p) {
    u64 v; asm("ld.global.nc.b64 %0, [%1];" : "=l"(v) : "l"(p)); return v;
}
__device__ __forceinline__ void stcs64(float* p, u64 v) {
    asm volatile("st.global.cs.b64 [%0], %1;" :: "l"(p), "l"(v) : "memory");
}

struct State {
    u64 s1a, s2a, s1b, s2b, s1c, s2c, s1d, s2d;
};

__device__ __forceinline__ u64 pipeline_step(u64 v, const CoeffsP& k, State& s)
{
    u64 y = biquad_bp(v, k.p0_b0, k.p0_b2, k.p0_na1, k.p0_na2, s.s1a, s.s2a);
    y     = biquad_bp(y, k.p1_b0, k.p1_b2, k.p1_na1, k.p1_na2, s.s1b, s.s2b);
    y     = mul2(y, y);
    y     = biquad_g(y, k.q0_b0, k.q0_b1, k.q0_b2, k.q0_na1, k.q0_na2, s.s1c, s.s2c);
    y     = biquad_g(y, k.q1_b0, k.q1_b1, k.q1_b2, k.q1_na1, k.q1_na2, s.s1d, s.s2d);
    return y;
}

__device__ __forceinline__ void ldgroup(u64* v, const float* p)
{
#pragma unroll
    for (int j = 0; j < GRP; ++j) v[j] = ldg64(p + j * CC);
}

// Compute one group of 8 steps; emit (warp-uniform) controls stores.
__device__ __forceinline__ void compute_group(const u64* v, const CoeffsP& k, State& st,
                                              bool emit, float*& op)
{
#pragma unroll
    for (int j = 0; j < GRP; ++j) {
        u64 y = pipeline_step(v[j], k, st);
        if (emit) stcs64(op + j * CC, y);
    }
    if (emit) op += GRP * CC;
}

__global__ void __launch_bounds__(128)
iir_chunked_kernel(const float* __restrict__ x,
                   const float* __restrict__ bp_sos,
                   const float* __restrict__ lp_sos,
                   float* __restrict__ out)
{
    const int c2    = threadIdx.x;                              // 0..31 (channel pair)
    const int b     = blockIdx.x;                               // 0..15 (batch)
    const int chunk = blockIdx.y * blockDim.y + threadIdx.y;    // 0..NCHUNK-1

    // ---- Load & normalize the 4 biquad sections (2 bp, 2 lp) ----
    // sos row layout: [b0, b1, b2, a0, a1, a2]
    CoeffsP k;
    {
        const float* r0 = bp_sos;
        const float* r1 = bp_sos + 6;
        const float* r2 = lp_sos;
        const float* r3 = lp_sos + 6;
        float i0 = 1.0f / r0[3], i1 = 1.0f / r1[3], i2 = 1.0f / r2[3], i3 = 1.0f / r3[3];
        k.p0_b0 = bcast2(r0[0] * i0); k.p0_b2 = bcast2(r0[2] * i0);
        k.p0_na1 = bcast2(-r0[4] * i0); k.p0_na2 = bcast2(-r0[5] * i0);
        k.p1_b0 = bcast2(r1[0] * i1); k.p1_b2 = bcast2(r1[2] * i1);
        k.p1_na1 = bcast2(-r1[4] * i1); k.p1_na2 = bcast2(-r1[5] * i1);
        k.q0_b0 = bcast2(r2[0] * i2); k.q0_b1 = bcast2(r2[1] * i2); k.q0_b2 = bcast2(r2[2] * i2);
        k.q0_na1 = bcast2(-r2[4] * i2); k.q0_na2 = bcast2(-r2[5] * i2);
        k.q1_b0 = bcast2(r3[0] * i3); k.q1_b1 = bcast2(r3[1] * i3); k.q1_b2 = bcast2(r3[2] * i3);
        k.q1_na1 = bcast2(-r3[4] * i3); k.q1_na2 = bcast2(-r3[5] * i3);
    }

    State st = {0, 0, 0, 0, 0, 0, 0, 0};

    const int t_out0 = chunk * CHUNK_L;
    const float* xm = x + ((size_t)b * TT + (size_t)t_out0) * CC + 2 * c2;   // main base
    float*       op = out + ((size_t)b * TT + (size_t)t_out0) * CC + 2 * c2;

    // Ping-pong buffers, one GRP=8 group each. No rotate copies; prefetch
    // distance = 8 steps (load for a buffer issues right after it's consumed,
    // consumed again after the other buffer's 8 steps).
    u64 A[GRP], B[GRP];

    if (chunk != 0) {   // warp-uniform branch (chunk fixed per warp)
        // Stream: groups g0..g12 (g0..g4 warmup, g5..g12 emitted).
        const float* xw = xm - (size_t)WARM * CC;
        ldgroup(A, xw);
        ldgroup(B, xw + (size_t)GRP * CC);
        compute_group(A, k, st, false, op);            // g0
        ldgroup(A, xw + (size_t)2 * GRP * CC);
#pragma unroll 1
        for (int it = 0; it < 5; ++it) {
            const int gB = 2 * it + 1, gA = 2 * it + 2;
            compute_group(B, k, st, gB >= WGRPS, op);  // g1,3,5,7,9
            ldgroup(B, xw + (size_t)(gB + 2) * GRP * CC);
            compute_group(A, k, st, gA >= WGRPS, op);  // g2,4,6,8,10
            ldgroup(A, xw + (size_t)(gA + 2) * GRP * CC);
        }
        compute_group(B, k, st, true, op);             // g11
        compute_group(A, k, st, true, op);             // g12
    } else {
        // Stream: groups g0..g7, all emitted, zero initial state at t=0.
        ldgroup(A, xm);
        ldgroup(B, xm + (size_t)GRP * CC);
#pragma unroll 1
        for (int it = 0; it < 3; ++it) {
            compute_group(A, k, st, true, op);         // g0,2,4
            ldgroup(A, xm + (size_t)(2 * it + 2) * GRP * CC);
            compute_group(B, k, st, true, op);         // g1,3,5
            ldgroup(B, xm + (size_t)(2 * it + 3) * GRP * CC);
        }
        compute_group(A, k, st, true, op);             // g6
        compute_group(B, k, st, true, op);             // g7
    }
}

extern "C" void kernel_launch(void* const* d_in, const int* in_sizes, int n_in,
                              void* d_out, int out_size)
{
    const float* x      = (const float*)d_in[0];
    const float* bp_sos = (const float*)d_in[1];
    const float* lp_sos = (const float*)d_in[2];
    float* out          = (float*)d_out;

    dim3 blk(32, 4);                 // 128 threads: 32 channel-pairs x 4 chunks
    dim3 grd(BB, NCHUNK / 4);        // 16 x 64 = 1024 blocks
    iir_chunked_kernel<<<grd, blk>>>(x, bp_sos, lp_sos, out);
}